// round 13
// baseline (speedup 1.0000x reference)
#include <cuda_runtime.h>
#include <cuda_fp16.h>
#include <math.h>

#ifndef M_PI
#define M_PI 3.14159265358979323846
#endif

#define NBETA   12
#define NAPAIR  6
#define NALPHA  12
#define DIM     36
#define NCH     128
#define NTYPE   10
#define WSIZE   (3 * NTYPE * NCH * 6)   // 23040

typedef unsigned long long ull;

// ---- packed f32x2 helpers ----
__device__ __forceinline__ ull pk2(float lo, float hi) {
    ull r; asm("mov.b64 %0, {%1, %2};" : "=l"(r) : "f"(lo), "f"(hi)); return r;
}
__device__ __forceinline__ void upk2(ull v, float& lo, float& hi) {
    asm("mov.b64 {%0, %1}, %2;" : "=f"(lo), "=f"(hi) : "l"(v));
}
__device__ __forceinline__ ull fma2(ull a, ull b, ull c) {
    ull d; asm("fma.rn.f32x2 %0, %1, %2, %3;" : "=l"(d) : "l"(a), "l"(b), "l"(c)); return d;
}

// ---- 12-point Gauss-Legendre nodes/weights ----
__constant__ double c_glx[NBETA] = {
    -0.9815606342467192, -0.9041172563704749, -0.7699026741943047,
    -0.5873179542866175, -0.3678314989981802, -0.1252334085114689,
     0.1252334085114689,  0.3678314989981802,  0.5873179542866175,
     0.7699026741943047,  0.9041172563704749,  0.9815606342467192
};
__constant__ double c_glw[NBETA] = {
    0.0471753363865118, 0.1069393259953184, 0.1600783285433462,
    0.2031674267230659, 0.2334925365383548, 0.2491470458134028,
    0.2491470458134028, 0.2334925365383548, 0.2031674267230659,
    0.1600783285433462, 0.1069393259953184, 0.0471753363865118
};

// Pair table: lane.lo -> k=PKA[i] (mi even = 2*PJT[i]), lane.hi -> k=PKB[i]
// (mi odd = 2*PJT[i]+1); -1 = zero lane. Covers all 36 k exactly once.
__constant__ int PKA[21] = {25,-1, 9,17,27,-1, 1, 5,11,19,29,-1, 3, 7,13,21,31,15,23,33,35};
__constant__ int PKB[21] = {16,26, 4,10,18,28, 0, 2, 6,12,20,30, 8,14,22,32,-1,24,34,-1,-1};
__constant__ int PJT[21] = { 0, 0, 1, 1, 1, 1, 2, 2, 2, 2, 2, 2, 3, 3, 3, 3, 3, 4, 4, 4, 5};

// Device table layout (floats):
//   [0,528)      PKP packed Pk   12 b x 22 entries x 2 (176 B/row)
//   [528,1056)   PWP packed Pwk  12 b x 22 entries x 2
#define OFF_PKP  0
#define OFF_PWP  528
#define TBL_SIZE 1056
#define OFF_AT   1056
#define HDR      1072
__device__ float g_tbl[TBL_SIZE];

__global__ void init_tables_kernel() {
    int t = threadIdx.x;
    if (t >= NBETA) return;
    double x = c_glx[t];
    double w = c_glw[t];
    double P[6][6];
    double s = sqrt(fmax(1.0 - x * x, 0.0));
    P[0][0] = sqrt(1.0 / (4.0 * M_PI));
    for (int m = 1; m <= 5; ++m)
        P[m][m] = sqrt((2.0 * m + 1.0) / (2.0 * m)) * s * P[m - 1][m - 1];
    for (int m = 0; m < 5; ++m)
        P[m + 1][m] = sqrt(2.0 * m + 3.0) * x * P[m][m];
    for (int m = 0; m <= 5; ++m)
        for (int l = m + 2; l <= 5; ++l) {
            double aa = sqrt((4.0 * l * l - 1.0) / ((double)l * l - (double)m * m));
            double bb = sqrt((((l - 1.0) * (l - 1.0)) - (double)m * m) /
                             (4.0 * (l - 1.0) * (l - 1.0) - 1.0));
            P[l][m] = aa * (x * P[l - 1][m] - bb * P[l - 2][m]);
        }
    double wfac = w * (2.0 * M_PI / (double)NALPHA);
    float Pk[DIM], Pw[DIM];
    for (int k = 0; k < DIM; ++k) {
        int l = 0;
        while (k >= (l + 1) * (l + 1)) ++l;
        int m = k - l * l - l;
        double v = P[l][m < 0 ? -m : m];
        Pk[k] = (float)v;
        Pw[k] = (float)(v * wfac);
    }
    for (int i = 0; i < 21; ++i) {
        int kA = PKA[i], kB = PKB[i];
        g_tbl[OFF_PKP + t * 44 + 2*i + 0] = (kA >= 0) ? Pk[kA] : 0.0f;
        g_tbl[OFF_PKP + t * 44 + 2*i + 1] = (kB >= 0) ? Pk[kB] : 0.0f;
        g_tbl[OFF_PWP + t * 44 + 2*i + 0] = (kA >= 0) ? Pw[kA] : 0.0f;
        g_tbl[OFF_PWP + t * 44 + 2*i + 1] = (kB >= 0) ? Pw[kB] : 0.0f;
    }
    g_tbl[OFF_PKP + t * 44 + 42] = 0.0f;  g_tbl[OFF_PKP + t * 44 + 43] = 0.0f;
    g_tbl[OFF_PWP + t * 44 + 42] = 0.0f;  g_tbl[OFF_PWP + t * 44 + 43] = 0.0f;
}

// Compile-time alpha trig constants: ANG[a][mi] = sqrt(2)*cos(m*a*pi/6) (mi=5+m),
// sqrt(2)*sin(m*a*pi/6) (mi=5-m), 1 at mi=5.  A0=0, A1=sqrt2, AH=sqrt2/2, AQ=sqrt6/2.
#define CA1 1.4142135623730951f
#define CAH 0.7071067811865476f
#define CAQ 1.2247448713915890f

// ---------------------------------------------------------------------------
// Main kernel: block = 1 atom, thread = 1 channel.
// to_grid/from_grid: packed FFMA2 against smem Pk/Pw tables.
// ap-loop: fully unrolled scalar FFMA with IMMEDIATE trig constants (rt=1).
// fp16x2 fg cache; 4 blocks/SM (live set ~110 regs fits the 128-reg cap now).
// ---------------------------------------------------------------------------
__global__ __launch_bounds__(NCH, 4) void tp_main_kernel(
    const float* __restrict__ feat,    // [n, 128, 36]
    const float* __restrict__ atype,   // [n, 10]
    const float* __restrict__ W,       // [3, 10, 128, 6]
    float* __restrict__ out)           // [n, 128, 36]
{
    constexpr int KA[21] = {25,-1, 9,17,27,-1, 1, 5,11,19,29,-1, 3, 7,13,21,31,15,23,33,35};
    constexpr int KB[21] = {16,26, 4,10,18,28, 0, 2, 6,12,20,30, 8,14,22,32,-1,24,34,-1,-1};
    constexpr int JT[21] = { 0, 0, 1, 1, 1, 1, 2, 2, 2, 2, 2, 2, 3, 3, 3, 3, 3, 4, 4, 4, 5};
    constexpr int KL[DIM] = {0,
                             1,1,1,
                             2,2,2,2,2,
                             3,3,3,3,3,3,3,
                             4,4,4,4,4,4,4,4,4,
                             5,5,5,5,5,5,5,5,5,5,5};
    constexpr float ANG[NAPAIR][11] = {
        {   0,    0,    0,    0,    0, 1.f,  CA1,  CA1,    0,  CA1,  CA1},  // a=0 (mi8 via ANG0_8)
        { CAH,  CAQ,  CA1,  CAQ,  CAH, 1.f,  CAQ,  CAH,    0, -CAH, -CAQ},  // a=1
        {-CAQ, -CAQ,    0,  CAQ,  CAQ, 1.f,  CAH, -CAH, -CA1, -CAH,  CAH},  // a=2
        { CA1,    0, -CA1,    0,  CA1, 1.f,    0, -CA1,    0,  CA1,    0},  // a=3
        {-CAQ,  CAQ,    0, -CAQ,  CAQ, 1.f, -CAH, -CAH,  CA1, -CAH, -CAH},  // a=4
        { CAH, -CAQ,  CA1, -CAQ,  CAH, 1.f, -CAQ,  CAH,    0, -CAH,  CAQ},  // a=5
    };
    constexpr float ANG0_8 = CA1;   // a=0: cos(3*0)=1

    extern __shared__ float sm[];
    float*   sAt = sm + OFF_AT;
    __half2* sFg = reinterpret_cast<__half2*>(sm + HDR);   // [b*6+ap][tid]

    const int tid = threadIdx.x;
    const int n   = blockIdx.x;

    for (int i = tid; i < TBL_SIZE; i += NCH) sm[i] = g_tbl[i];
    if (tid < NTYPE) sAt[tid] = atype[(size_t)n * NTYPE + tid];
    __syncthreads();

    const size_t base = ((size_t)n * NCH + tid) * DIM;

    // ---- load coefficients; build packed operand set for pass A ----
    ull cpk[21];
    {
        float c0[DIM];
        const float4* fp = reinterpret_cast<const float4*>(feat + base);
        #pragma unroll
        for (int q = 0; q < 9; ++q) {
            float4 v = fp[q];
            c0[4*q+0] = v.x; c0[4*q+1] = v.y; c0[4*q+2] = v.z; c0[4*q+3] = v.w;
        }
        #pragma unroll
        for (int i = 0; i < 21; ++i)
            cpk[i] = pk2(KA[i] >= 0 ? c0[KA[i]] : 0.0f,
                         KB[i] >= 0 ? c0[KB[i]] : 0.0f);
    }

    // =================== pass A: fg = Y c0 ; p1 = Yw^T (fg*fg) ===============
    ull p1p[21];
    #pragma unroll
    for (int i = 0; i < 21; ++i) p1p[i] = 0ULL;

    #pragma unroll 1
    for (int b = 0; b < NBETA; ++b) {
        const ull* pkr = reinterpret_cast<const ull*>(sm + OFF_PKP) + b * 22;
        ull t2[6] = {0,0,0,0,0,0};
        #pragma unroll
        for (int i = 0; i < 21; ++i) t2[JT[i]] = fma2(pkr[i], cpk[i], t2[JT[i]]);

        float t[11];
        #pragma unroll
        for (int j = 0; j < 5; ++j) upk2(t2[j], t[2*j], t[2*j+1]);
        { float junk; upk2(t2[5], t[10], junk); }

        float u[11];
        #pragma unroll
        for (int mi = 0; mi < 11; ++mi) u[mi] = 0.f;

        #pragma unroll
        for (int ap = 0; ap < NAPAIR; ++ap) {
            float fe = 0.f, fo = 0.f;
            #pragma unroll
            for (int mi = 0; mi < 11; ++mi) {
                float av = (ap == 0 && mi == 8) ? ANG0_8 : ANG[ap][mi];
                if (av != 0.f) {
                    if (mi & 1) fe = fmaf(t[mi], av, fe);
                    else        fo = fmaf(t[mi], av, fo);
                }
            }
            float f1 = fe + fo, f2 = fe - fo;
            sFg[(b * NAPAIR + ap) * NCH + tid] = __floats2half2_rn(f1, f2);
            float g1 = f1 * f1, g2 = f2 * f2;
            float gs = g1 + g2, gd = g1 - g2;
            #pragma unroll
            for (int mi = 0; mi < 11; ++mi) {
                float av = (ap == 0 && mi == 8) ? ANG0_8 : ANG[ap][mi];
                if (av != 0.f)
                    u[mi] = fmaf((mi & 1) ? gs : gd, av, u[mi]);
            }
        }

        ull u2[6];
        #pragma unroll
        for (int j = 0; j < 5; ++j) u2[j] = pk2(u[2*j], u[2*j+1]);
        u2[5] = pk2(u[10], 0.f);

        const ull* pwr = reinterpret_cast<const ull*>(sm + OFF_PWP) + b * 22;
        #pragma unroll
        for (int i = 0; i < 21; ++i) p1p[i] = fma2(pwr[i], u2[JT[i]], p1p[i]);
    }

    // ============ pass B: p2 = Yw^T ((Y p1) * fg) ============================
    ull p2p[21];
    #pragma unroll
    for (int i = 0; i < 21; ++i) p2p[i] = 0ULL;

    #pragma unroll 1
    for (int b = 0; b < NBETA; ++b) {
        const ull* pkr = reinterpret_cast<const ull*>(sm + OFF_PKP) + b * 22;
        ull t2[6] = {0,0,0,0,0,0};
        #pragma unroll
        for (int i = 0; i < 21; ++i) t2[JT[i]] = fma2(pkr[i], p1p[i], t2[JT[i]]);

        float t[11];
        #pragma unroll
        for (int j = 0; j < 5; ++j) upk2(t2[j], t[2*j], t[2*j+1]);
        { float junk; upk2(t2[5], t[10], junk); }

        float u[11];
        #pragma unroll
        for (int mi = 0; mi < 11; ++mi) u[mi] = 0.f;

        #pragma unroll
        for (int ap = 0; ap < NAPAIR; ++ap) {
            float fe = 0.f, fo = 0.f;
            #pragma unroll
            for (int mi = 0; mi < 11; ++mi) {
                float av = (ap == 0 && mi == 8) ? ANG0_8 : ANG[ap][mi];
                if (av != 0.f) {
                    if (mi & 1) fe = fmaf(t[mi], av, fe);
                    else        fo = fmaf(t[mi], av, fo);
                }
            }
            float2 fg = __half22float2(sFg[(b * NAPAIR + ap) * NCH + tid]);
            float g1 = (fe + fo) * fg.x;
            float g2 = (fe - fo) * fg.y;
            float gs = g1 + g2, gd = g1 - g2;
            #pragma unroll
            for (int mi = 0; mi < 11; ++mi) {
                float av = (ap == 0 && mi == 8) ? ANG0_8 : ANG[ap][mi];
                if (av != 0.f)
                    u[mi] = fmaf((mi & 1) ? gs : gd, av, u[mi]);
            }
        }

        ull u2[6];
        #pragma unroll
        for (int j = 0; j < 5; ++j) u2[j] = pk2(u[2*j], u[2*j+1]);
        u2[5] = pk2(u[10], 0.f);

        const ull* pwr = reinterpret_cast<const ull*>(sm + OFF_PWP) + b * 22;
        #pragma unroll
        for (int i = 0; i < 21; ++i) p2p[i] = fma2(pwr[i], u2[JT[i]], p2p[i]);
    }

    // ---- weights ----
    float w0[6], w1[6], w2[6];
    #pragma unroll
    for (int l = 0; l < 6; ++l) { w0[l] = 0.f; w1[l] = 0.f; w2[l] = 0.f; }
    #pragma unroll 1
    for (int e = 0; e < NTYPE; ++e) {
        float a = sAt[e];
        const float* Wp = W + ((size_t)e * NCH + tid) * 6;
        #pragma unroll
        for (int l = 0; l < 6; ++l) {
            w0[l] = fmaf(a, Wp[l],                       w0[l]);
            w1[l] = fmaf(a, Wp[NTYPE * NCH * 6 + l],     w1[l]);
            w2[l] = fmaf(a, Wp[2 * NTYPE * NCH * 6 + l], w2[l]);
        }
    }

    // ---- unpack p1/p2, reload c0, combine, store ----
    float p1s[DIM], p2s[DIM];
    #pragma unroll
    for (int i = 0; i < 21; ++i) {
        float lo, hi;
        upk2(p1p[i], lo, hi);
        if (KA[i] >= 0) p1s[KA[i]] = lo;
        if (KB[i] >= 0) p1s[KB[i]] = hi;
        upk2(p2p[i], lo, hi);
        if (KA[i] >= 0) p2s[KA[i]] = lo;
        if (KB[i] >= 0) p2s[KB[i]] = hi;
    }

    const float4* fp = reinterpret_cast<const float4*>(feat + base);
    float* op = out + base;
    #pragma unroll
    for (int q = 0; q < 9; ++q) {
        float4 cv = fp[q];
        float4 v;
        v.x = fmaf(w0[KL[4*q+0]], cv.x, fmaf(w1[KL[4*q+0]], p1s[4*q+0], w2[KL[4*q+0]] * p2s[4*q+0]));
        v.y = fmaf(w0[KL[4*q+1]], cv.y, fmaf(w1[KL[4*q+1]], p1s[4*q+1], w2[KL[4*q+1]] * p2s[4*q+1]));
        v.z = fmaf(w0[KL[4*q+2]], cv.z, fmaf(w1[KL[4*q+2]], p1s[4*q+2], w2[KL[4*q+2]] * p2s[4*q+2]));
        v.w = fmaf(w0[KL[4*q+3]], cv.w, fmaf(w1[KL[4*q+3]], p1s[4*q+3], w2[KL[4*q+3]] * p2s[4*q+3]));
        *reinterpret_cast<float4*>(op + 4 * q) = v;
    }
}

// ---------------------------------------------------------------------------
extern "C" void kernel_launch(void* const* d_in, const int* in_sizes, int n_in,
                              void* d_out, int out_size) {
    // Bind inputs BY SIZE: feat = largest (n*128*36), W = 23040, atype = n*10
    const float* feat  = nullptr;
    const float* atype = nullptr;
    const float* W     = nullptr;

    int fi = 0;
    for (int i = 1; i < n_in; ++i) if (in_sizes[i] > in_sizes[fi]) fi = i;
    feat = (const float*)d_in[fi];
    int n_atoms = in_sizes[fi] / (NCH * DIM);

    for (int i = 0; i < n_in; ++i) {
        if (i == fi) continue;
        if (in_sizes[i] == WSIZE && W == nullptr && in_sizes[i] != n_atoms * NTYPE) {
            W = (const float*)d_in[i];
        } else if (in_sizes[i] == n_atoms * NTYPE && atype == nullptr) {
            atype = (const float*)d_in[i];
        } else if (W == nullptr) {
            W = (const float*)d_in[i];
        } else {
            atype = (const float*)d_in[i];
        }
    }
    if (!atype) atype = (const float*)d_in[1];
    if (!W)     W     = (const float*)d_in[2];

    float* out = (float*)d_out;

    // smem: HDR floats + 12*6*128 half2 fg = 4288 + 36864 = 41152 B
    size_t smem = (size_t)HDR * sizeof(float) +
                  (size_t)NBETA * NAPAIR * NCH * sizeof(__half2);
    cudaFuncSetAttribute(tp_main_kernel,
                         cudaFuncAttributeMaxDynamicSharedMemorySize, (int)smem);

    init_tables_kernel<<<1, 32>>>();
    tp_main_kernel<<<n_atoms, NCH, smem>>>(feat, atype, W, out);
}

// round 14
// speedup vs baseline: 1.2762x; 1.2762x over previous
#include <cuda_runtime.h>
#include <cuda_fp16.h>
#include <math.h>

#ifndef M_PI
#define M_PI 3.14159265358979323846
#endif

#define NBETA   12
#define NAPAIR  6
#define NALPHA  12
#define DIM     36
#define NCH     128
#define NTYPE   10
#define WSIZE   (3 * NTYPE * NCH * 6)   // 23040

typedef unsigned long long ull;

// ---- packed f32x2 helpers ----
__device__ __forceinline__ ull pk2(float lo, float hi) {
    ull r; asm("mov.b64 %0, {%1, %2};" : "=l"(r) : "f"(lo), "f"(hi)); return r;
}
__device__ __forceinline__ void upk2(ull v, float& lo, float& hi) {
    asm("mov.b64 {%0, %1}, %2;" : "=f"(lo), "=f"(hi) : "l"(v));
}
__device__ __forceinline__ ull fma2(ull a, ull b, ull c) {
    ull d; asm("fma.rn.f32x2 %0, %1, %2, %3;" : "=l"(d) : "l"(a), "l"(b), "l"(c)); return d;
}

// ---- 12-point Gauss-Legendre nodes/weights ----
__constant__ double c_glx[NBETA] = {
    -0.9815606342467192, -0.9041172563704749, -0.7699026741943047,
    -0.5873179542866175, -0.3678314989981802, -0.1252334085114689,
     0.1252334085114689,  0.3678314989981802,  0.5873179542866175,
     0.7699026741943047,  0.9041172563704749,  0.9815606342467192
};
__constant__ double c_glw[NBETA] = {
    0.0471753363865118, 0.1069393259953184, 0.1600783285433462,
    0.2031674267230659, 0.2334925365383548, 0.2491470458134028,
    0.2491470458134028, 0.2334925365383548, 0.2031674267230659,
    0.1600783285433462, 0.1069393259953184, 0.0471753363865118
};

// Pair table: lane.lo -> k=PKA[i] (mi even = 2*PJT[i]), lane.hi -> k=PKB[i]
// (mi odd = 2*PJT[i]+1); -1 = zero lane. Covers all 36 k exactly once.
__constant__ int PKA[21] = {25,-1, 9,17,27,-1, 1, 5,11,19,29,-1, 3, 7,13,21,31,15,23,33,35};
__constant__ int PKB[21] = {16,26, 4,10,18,28, 0, 2, 6,12,20,30, 8,14,22,32,-1,24,34,-1,-1};
__constant__ int PJT[21] = { 0, 0, 1, 1, 1, 1, 2, 2, 2, 2, 2, 2, 3, 3, 3, 3, 3, 4, 4, 4, 5};

// Device table layout (floats):
//   [0,528)      PKP packed Pk   12 b x 22 entries x 2 (176 B/row)
//   [528,1056)   PWP packed Pwk  12 b x 22 entries x 2
#define OFF_PKP  0
#define OFF_PWP  528
#define TBL_SIZE 1056
#define OFF_AT   1056
#define HDR      1072
__device__ float g_tbl[TBL_SIZE];

__global__ void init_tables_kernel() {
    int t = threadIdx.x;
    if (t >= NBETA) return;
    double x = c_glx[t];
    double w = c_glw[t];
    double P[6][6];
    double s = sqrt(fmax(1.0 - x * x, 0.0));
    P[0][0] = sqrt(1.0 / (4.0 * M_PI));
    for (int m = 1; m <= 5; ++m)
        P[m][m] = sqrt((2.0 * m + 1.0) / (2.0 * m)) * s * P[m - 1][m - 1];
    for (int m = 0; m < 5; ++m)
        P[m + 1][m] = sqrt(2.0 * m + 3.0) * x * P[m][m];
    for (int m = 0; m <= 5; ++m)
        for (int l = m + 2; l <= 5; ++l) {
            double aa = sqrt((4.0 * l * l - 1.0) / ((double)l * l - (double)m * m));
            double bb = sqrt((((l - 1.0) * (l - 1.0)) - (double)m * m) /
                             (4.0 * (l - 1.0) * (l - 1.0) - 1.0));
            P[l][m] = aa * (x * P[l - 1][m] - bb * P[l - 2][m]);
        }
    double wfac = w * (2.0 * M_PI / (double)NALPHA);
    float Pk[DIM], Pw[DIM];
    for (int k = 0; k < DIM; ++k) {
        int l = 0;
        while (k >= (l + 1) * (l + 1)) ++l;
        int m = k - l * l - l;
        double v = P[l][m < 0 ? -m : m];
        Pk[k] = (float)v;
        Pw[k] = (float)(v * wfac);
    }
    for (int i = 0; i < 21; ++i) {
        int kA = PKA[i], kB = PKB[i];
        g_tbl[OFF_PKP + t * 44 + 2*i + 0] = (kA >= 0) ? Pk[kA] : 0.0f;
        g_tbl[OFF_PKP + t * 44 + 2*i + 1] = (kB >= 0) ? Pk[kB] : 0.0f;
        g_tbl[OFF_PWP + t * 44 + 2*i + 0] = (kA >= 0) ? Pw[kA] : 0.0f;
        g_tbl[OFF_PWP + t * 44 + 2*i + 1] = (kB >= 0) ? Pw[kB] : 0.0f;
    }
    g_tbl[OFF_PKP + t * 44 + 42] = 0.0f;  g_tbl[OFF_PKP + t * 44 + 43] = 0.0f;
    g_tbl[OFF_PWP + t * 44 + 42] = 0.0f;  g_tbl[OFF_PWP + t * 44 + 43] = 0.0f;
}

// alpha trig immediates
#define CA1 1.4142135623730951f
#define CAH 0.7071067811865476f
#define CAQ 1.2247448713915890f

// ---------------------------------------------------------------------------
// Main kernel: block = 1 atom, thread = 1 channel, 3 blocks/SM (168 regs).
// to_grid/from_grid: packed FFMA2 vs smem Pk/Pw.
// ap work: BOTH alpha symmetries — pairing alpha+pi (fe/fo) AND reflection
// pi-alpha (groups {1,5},{2,4} via feC/feS/foC/foS partials; 4 alphas per
// partial set; u-accum on sign-combined gsP/gsM/gdP/gdM). Immediate trig.
// fp16x2 fg cache.
// ---------------------------------------------------------------------------
__global__ __launch_bounds__(NCH, 3) void tp_main_kernel(
    const float* __restrict__ feat,    // [n, 128, 36]
    const float* __restrict__ atype,   // [n, 10]
    const float* __restrict__ W,       // [3, 10, 128, 6]
    float* __restrict__ out)           // [n, 128, 36]
{
    constexpr int KA[21] = {25,-1, 9,17,27,-1, 1, 5,11,19,29,-1, 3, 7,13,21,31,15,23,33,35};
    constexpr int KB[21] = {16,26, 4,10,18,28, 0, 2, 6,12,20,30, 8,14,22,32,-1,24,34,-1,-1};
    constexpr int JT[21] = { 0, 0, 1, 1, 1, 1, 2, 2, 2, 2, 2, 2, 3, 3, 3, 3, 3, 4, 4, 4, 5};
    constexpr int KL[DIM] = {0,
                             1,1,1,
                             2,2,2,2,2,
                             3,3,3,3,3,3,3,
                             4,4,4,4,4,4,4,4,4,
                             5,5,5,5,5,5,5,5,5,5,5};

    extern __shared__ float sm[];
    float*   sAt = sm + OFF_AT;
    __half2* sFg = reinterpret_cast<__half2*>(sm + HDR);   // [b*6+ap][tid]

    const int tid = threadIdx.x;
    const int n   = blockIdx.x;

    for (int i = tid; i < TBL_SIZE; i += NCH) sm[i] = g_tbl[i];
    if (tid < NTYPE) sAt[tid] = atype[(size_t)n * NTYPE + tid];
    __syncthreads();

    const size_t base = ((size_t)n * NCH + tid) * DIM;

    // ---- load coefficients; packed operands for pass A ----
    ull cpk[21];
    {
        float c0[DIM];
        const float4* fp = reinterpret_cast<const float4*>(feat + base);
        #pragma unroll
        for (int q = 0; q < 9; ++q) {
            float4 v = fp[q];
            c0[4*q+0] = v.x; c0[4*q+1] = v.y; c0[4*q+2] = v.z; c0[4*q+3] = v.w;
        }
        #pragma unroll
        for (int i = 0; i < 21; ++i)
            cpk[i] = pk2(KA[i] >= 0 ? c0[KA[i]] : 0.0f,
                         KB[i] >= 0 ? c0[KB[i]] : 0.0f);
    }

    // =================== pass A ==============================================
    ull p1p[21];
    #pragma unroll
    for (int i = 0; i < 21; ++i) p1p[i] = 0ULL;

    #pragma unroll 1
    for (int b = 0; b < NBETA; ++b) {
        const ull* pkr = reinterpret_cast<const ull*>(sm + OFF_PKP) + b * 22;
        ull t2[6] = {0,0,0,0,0,0};
        #pragma unroll
        for (int i = 0; i < 21; ++i) t2[JT[i]] = fma2(pkr[i], cpk[i], t2[JT[i]]);

        float t[11];
        #pragma unroll
        for (int j = 0; j < 5; ++j) upk2(t2[j], t[2*j], t[2*j+1]);
        { float junk; upk2(t2[5], t[10], junk); }

        float u0=0,u1=0,u2v=0,u3=0,u4=0,u5=0,u6=0,u7=0,u8=0,u9=0,u10=0;
        __half2* fgrow = sFg + b * NAPAIR * NCH + tid;

        // ---- singleton ap=0 (alpha=0) ----
        {
            float fe = fmaf(CA1, t[7], fmaf(CA1, t[9], t[5]));
            float fo = fmaf(CA1, t[6], fmaf(CA1, t[8], CA1 * t[10]));
            float f1 = fe + fo, f2 = fe - fo;
            fgrow[0 * NCH] = __floats2half2_rn(f1, f2);
            float q1 = f1 * f1, q2 = f2 * f2;
            float gs = q1 + q2, gd = q1 - q2;
            u5 += gs;
            u7 = fmaf(gs, CA1, u7);  u9  = fmaf(gs, CA1, u9);
            u6 = fmaf(gd, CA1, u6);  u8  = fmaf(gd, CA1, u8);
            u10 = fmaf(gd, CA1, u10);
        }
        // ---- singleton ap=3 (alpha=pi/2) ----
        {
            float fe = fmaf(-CA1, t[7], fmaf(CA1, t[9], t[5]));
            float fo = fmaf(CA1, t[0], fmaf(-CA1, t[2], CA1 * t[4]));
            float f1 = fe + fo, f2 = fe - fo;
            fgrow[3 * NCH] = __floats2half2_rn(f1, f2);
            float q1 = f1 * f1, q2 = f2 * f2;
            float gs = q1 + q2, gd = q1 - q2;
            u5 += gs;
            u7 = fmaf(gs, -CA1, u7);  u9 = fmaf(gs, CA1, u9);
            u0 = fmaf(gd, CA1, u0);   u2v = fmaf(gd, -CA1, u2v);
            u4 = fmaf(gd, CA1, u4);
        }
        // ---- group {1,5} (row ap=1) ----
        {
            float feC = fmaf(CAH, t[7], fmaf(-CAH, t[9], t[5]));
            float feS = fmaf(CAQ, t[1], CAQ * t[3]);
            float foC = fmaf(-CAQ, t[10], CAQ * t[6]);
            float foS = fmaf(CAH, t[0], fmaf(CA1, t[2], CAH * t[4]));
            float fea = feC + feS, foa = foC + foS;
            float feb = feC - feS, fob = foS - foC;
            float f1a = fea + foa, f2a = fea - foa;
            float f1b = feb + fob, f2b = feb - fob;
            fgrow[1 * NCH] = __floats2half2_rn(f1a, f2a);
            fgrow[5 * NCH] = __floats2half2_rn(f1b, f2b);
            float qa1 = f1a * f1a, qa2 = f2a * f2a;
            float qb1 = f1b * f1b, qb2 = f2b * f2b;
            float gsa = qa1 + qa2, gda = qa1 - qa2;
            float gsb = qb1 + qb2, gdb = qb1 - qb2;
            float gsP = gsa + gsb, gsM = gsa - gsb;
            float gdP = gda + gdb, gdM = gda - gdb;
            u5 += gsP;
            u7 = fmaf(gsP, CAH, u7);   u9  = fmaf(gsP, -CAH, u9);
            u1 = fmaf(gsM, CAQ, u1);   u3  = fmaf(gsM, CAQ, u3);
            u0 = fmaf(gdP, CAH, u0);   u2v = fmaf(gdP, CA1, u2v);
            u4 = fmaf(gdP, CAH, u4);
            u6 = fmaf(gdM, CAQ, u6);   u10 = fmaf(gdM, -CAQ, u10);
        }
        // ---- group {2,4} (row ap=2) ----
        {
            float feC = fmaf(-CAH, t[7], fmaf(-CAH, t[9], t[5]));
            float feS = fmaf(-CAQ, t[1], CAQ * t[3]);
            float foC = fmaf(CAH, t[6], fmaf(-CA1, t[8], CAH * t[10]));
            float foS = fmaf(-CAQ, t[0], CAQ * t[4]);
            float fea = feC + feS, foa = foC + foS;
            float feb = feC - feS, fob = foS - foC;
            float f1a = fea + foa, f2a = fea - foa;
            float f1b = feb + fob, f2b = feb - fob;
            fgrow[2 * NCH] = __floats2half2_rn(f1a, f2a);
            fgrow[4 * NCH] = __floats2half2_rn(f1b, f2b);
            float qa1 = f1a * f1a, qa2 = f2a * f2a;
            float qb1 = f1b * f1b, qb2 = f2b * f2b;
            float gsa = qa1 + qa2, gda = qa1 - qa2;
            float gsb = qb1 + qb2, gdb = qb1 - qb2;
            float gsP = gsa + gsb, gsM = gsa - gsb;
            float gdP = gda + gdb, gdM = gda - gdb;
            u5 += gsP;
            u7 = fmaf(gsP, -CAH, u7);  u9  = fmaf(gsP, -CAH, u9);
            u1 = fmaf(gsM, -CAQ, u1);  u3  = fmaf(gsM, CAQ, u3);
            u0 = fmaf(gdP, -CAQ, u0);  u4  = fmaf(gdP, CAQ, u4);
            u6 = fmaf(gdM, CAH, u6);   u8  = fmaf(gdM, -CA1, u8);
            u10 = fmaf(gdM, CAH, u10);
        }

        ull uu[6];
        uu[0] = pk2(u0, u1);  uu[1] = pk2(u2v, u3);  uu[2] = pk2(u4, u5);
        uu[3] = pk2(u6, u7);  uu[4] = pk2(u8, u9);   uu[5] = pk2(u10, 0.f);

        const ull* pwr = reinterpret_cast<const ull*>(sm + OFF_PWP) + b * 22;
        #pragma unroll
        for (int i = 0; i < 21; ++i) p1p[i] = fma2(pwr[i], uu[JT[i]], p1p[i]);
    }

    // =================== pass B ==============================================
    ull p2p[21];
    #pragma unroll
    for (int i = 0; i < 21; ++i) p2p[i] = 0ULL;

    #pragma unroll 1
    for (int b = 0; b < NBETA; ++b) {
        const ull* pkr = reinterpret_cast<const ull*>(sm + OFF_PKP) + b * 22;
        ull t2[6] = {0,0,0,0,0,0};
        #pragma unroll
        for (int i = 0; i < 21; ++i) t2[JT[i]] = fma2(pkr[i], p1p[i], t2[JT[i]]);

        float t[11];
        #pragma unroll
        for (int j = 0; j < 5; ++j) upk2(t2[j], t[2*j], t[2*j+1]);
        { float junk; upk2(t2[5], t[10], junk); }

        float u0=0,u1=0,u2v=0,u3=0,u4=0,u5=0,u6=0,u7=0,u8=0,u9=0,u10=0;
        const __half2* fgrow = sFg + b * NAPAIR * NCH + tid;

        // ---- singleton ap=0 ----
        {
            float fe = fmaf(CA1, t[7], fmaf(CA1, t[9], t[5]));
            float fo = fmaf(CA1, t[6], fmaf(CA1, t[8], CA1 * t[10]));
            float2 fg = __half22float2(fgrow[0 * NCH]);
            float g1 = (fe + fo) * fg.x, g2 = (fe - fo) * fg.y;
            float gs = g1 + g2, gd = g1 - g2;
            u5 += gs;
            u7 = fmaf(gs, CA1, u7);  u9  = fmaf(gs, CA1, u9);
            u6 = fmaf(gd, CA1, u6);  u8  = fmaf(gd, CA1, u8);
            u10 = fmaf(gd, CA1, u10);
        }
        // ---- singleton ap=3 ----
        {
            float fe = fmaf(-CA1, t[7], fmaf(CA1, t[9], t[5]));
            float fo = fmaf(CA1, t[0], fmaf(-CA1, t[2], CA1 * t[4]));
            float2 fg = __half22float2(fgrow[3 * NCH]);
            float g1 = (fe + fo) * fg.x, g2 = (fe - fo) * fg.y;
            float gs = g1 + g2, gd = g1 - g2;
            u5 += gs;
            u7 = fmaf(gs, -CA1, u7);  u9 = fmaf(gs, CA1, u9);
            u0 = fmaf(gd, CA1, u0);   u2v = fmaf(gd, -CA1, u2v);
            u4 = fmaf(gd, CA1, u4);
        }
        // ---- group {1,5} ----
        {
            float feC = fmaf(CAH, t[7], fmaf(-CAH, t[9], t[5]));
            float feS = fmaf(CAQ, t[1], CAQ * t[3]);
            float foC = fmaf(-CAQ, t[10], CAQ * t[6]);
            float foS = fmaf(CAH, t[0], fmaf(CA1, t[2], CAH * t[4]));
            float fea = feC + feS, foa = foC + foS;
            float feb = feC - feS, fob = foS - foC;
            float2 fga = __half22float2(fgrow[1 * NCH]);
            float2 fgb = __half22float2(fgrow[5 * NCH]);
            float g1a = (fea + foa) * fga.x, g2a = (fea - foa) * fga.y;
            float g1b = (feb + fob) * fgb.x, g2b = (feb - fob) * fgb.y;
            float gsa = g1a + g2a, gda = g1a - g2a;
            float gsb = g1b + g2b, gdb = g1b - g2b;
            float gsP = gsa + gsb, gsM = gsa - gsb;
            float gdP = gda + gdb, gdM = gda - gdb;
            u5 += gsP;
            u7 = fmaf(gsP, CAH, u7);   u9  = fmaf(gsP, -CAH, u9);
            u1 = fmaf(gsM, CAQ, u1);   u3  = fmaf(gsM, CAQ, u3);
            u0 = fmaf(gdP, CAH, u0);   u2v = fmaf(gdP, CA1, u2v);
            u4 = fmaf(gdP, CAH, u4);
            u6 = fmaf(gdM, CAQ, u6);   u10 = fmaf(gdM, -CAQ, u10);
        }
        // ---- group {2,4} ----
        {
            float feC = fmaf(-CAH, t[7], fmaf(-CAH, t[9], t[5]));
            float feS = fmaf(-CAQ, t[1], CAQ * t[3]);
            float foC = fmaf(CAH, t[6], fmaf(-CA1, t[8], CAH * t[10]));
            float foS = fmaf(-CAQ, t[0], CAQ * t[4]);
            float fea = feC + feS, foa = foC + foS;
            float feb = feC - feS, fob = foS - foC;
            float2 fga = __half22float2(fgrow[2 * NCH]);
            float2 fgb = __half22float2(fgrow[4 * NCH]);
            float g1a = (fea + foa) * fga.x, g2a = (fea - foa) * fga.y;
            float g1b = (feb + fob) * fgb.x, g2b = (feb - fob) * fgb.y;
            float gsa = g1a + g2a, gda = g1a - g2a;
            float gsb = g1b + g2b, gdb = g1b - g2b;
            float gsP = gsa + gsb, gsM = gsa - gsb;
            float gdP = gda + gdb, gdM = gda - gdb;
            u5 += gsP;
            u7 = fmaf(gsP, -CAH, u7);  u9  = fmaf(gsP, -CAH, u9);
            u1 = fmaf(gsM, -CAQ, u1);  u3  = fmaf(gsM, CAQ, u3);
            u0 = fmaf(gdP, -CAQ, u0);  u4  = fmaf(gdP, CAQ, u4);
            u6 = fmaf(gdM, CAH, u6);   u8  = fmaf(gdM, -CA1, u8);
            u10 = fmaf(gdM, CAH, u10);
        }

        ull uu[6];
        uu[0] = pk2(u0, u1);  uu[1] = pk2(u2v, u3);  uu[2] = pk2(u4, u5);
        uu[3] = pk2(u6, u7);  uu[4] = pk2(u8, u9);   uu[5] = pk2(u10, 0.f);

        const ull* pwr = reinterpret_cast<const ull*>(sm + OFF_PWP) + b * 22;
        #pragma unroll
        for (int i = 0; i < 21; ++i) p2p[i] = fma2(pwr[i], uu[JT[i]], p2p[i]);
    }

    // ---- weights ----
    float w0[6], w1[6], w2[6];
    #pragma unroll
    for (int l = 0; l < 6; ++l) { w0[l] = 0.f; w1[l] = 0.f; w2[l] = 0.f; }
    #pragma unroll 1
    for (int e = 0; e < NTYPE; ++e) {
        float a = sAt[e];
        const float* Wp = W + ((size_t)e * NCH + tid) * 6;
        #pragma unroll
        for (int l = 0; l < 6; ++l) {
            w0[l] = fmaf(a, Wp[l],                       w0[l]);
            w1[l] = fmaf(a, Wp[NTYPE * NCH * 6 + l],     w1[l]);
            w2[l] = fmaf(a, Wp[2 * NTYPE * NCH * 6 + l], w2[l]);
        }
    }

    // ---- unpack p1/p2, reload c0, combine, store ----
    float p1s[DIM], p2s[DIM];
    #pragma unroll
    for (int i = 0; i < 21; ++i) {
        float lo, hi;
        upk2(p1p[i], lo, hi);
        if (KA[i] >= 0) p1s[KA[i]] = lo;
        if (KB[i] >= 0) p1s[KB[i]] = hi;
        upk2(p2p[i], lo, hi);
        if (KA[i] >= 0) p2s[KA[i]] = lo;
        if (KB[i] >= 0) p2s[KB[i]] = hi;
    }

    const float4* fp = reinterpret_cast<const float4*>(feat + base);
    float* op = out + base;
    #pragma unroll
    for (int q = 0; q < 9; ++q) {
        float4 cv = fp[q];
        float4 v;
        v.x = fmaf(w0[KL[4*q+0]], cv.x, fmaf(w1[KL[4*q+0]], p1s[4*q+0], w2[KL[4*q+0]] * p2s[4*q+0]));
        v.y = fmaf(w0[KL[4*q+1]], cv.y, fmaf(w1[KL[4*q+1]], p1s[4*q+1], w2[KL[4*q+1]] * p2s[4*q+1]));
        v.z = fmaf(w0[KL[4*q+2]], cv.z, fmaf(w1[KL[4*q+2]], p1s[4*q+2], w2[KL[4*q+2]] * p2s[4*q+2]));
        v.w = fmaf(w0[KL[4*q+3]], cv.w, fmaf(w1[KL[4*q+3]], p1s[4*q+3], w2[KL[4*q+3]] * p2s[4*q+3]));
        *reinterpret_cast<float4*>(op + 4 * q) = v;
    }
}

// ---------------------------------------------------------------------------
extern "C" void kernel_launch(void* const* d_in, const int* in_sizes, int n_in,
                              void* d_out, int out_size) {
    // Bind inputs BY SIZE: feat = largest (n*128*36), W = 23040, atype = n*10
    const float* feat  = nullptr;
    const float* atype = nullptr;
    const float* W     = nullptr;

    int fi = 0;
    for (int i = 1; i < n_in; ++i) if (in_sizes[i] > in_sizes[fi]) fi = i;
    feat = (const float*)d_in[fi];
    int n_atoms = in_sizes[fi] / (NCH * DIM);

    for (int i = 0; i < n_in; ++i) {
        if (i == fi) continue;
        if (in_sizes[i] == WSIZE && W == nullptr && in_sizes[i] != n_atoms * NTYPE) {
            W = (const float*)d_in[i];
        } else if (in_sizes[i] == n_atoms * NTYPE && atype == nullptr) {
            atype = (const float*)d_in[i];
        } else if (W == nullptr) {
            W = (const float*)d_in[i];
        } else {
            atype = (const float*)d_in[i];
        }
    }
    if (!atype) atype = (const float*)d_in[1];
    if (!W)     W     = (const float*)d_in[2];

    float* out = (float*)d_out;

    // smem: HDR floats + 12*6*128 half2 fg = 4288 + 36864 = 41152 B
    size_t smem = (size_t)HDR * sizeof(float) +
                  (size_t)NBETA * NAPAIR * NCH * sizeof(__half2);
    cudaFuncSetAttribute(tp_main_kernel,
                         cudaFuncAttributeMaxDynamicSharedMemorySize, (int)smem);

    init_tables_kernel<<<1, 32>>>();
    tp_main_kernel<<<n_atoms, NCH, smem>>>(feat, atype, W, out);
}

// round 15
// speedup vs baseline: 1.3298x; 1.0420x over previous
#include <cuda_runtime.h>
#include <cuda_fp16.h>
#include <math.h>

#define NBETA   12
#define NAPAIR  6
#define NALPHA  12
#define DIM     36
#define NCH     128
#define NTYPE   10
#define WSIZE   (3 * NTYPE * NCH * 6)   // 23040

// ---------------------------------------------------------------------------
// Compile-time Gauss-Legendre + normalized associated Legendre tables.
// ---------------------------------------------------------------------------
__host__ __device__ constexpr double csqrt_(double x) {
    if (x <= 0.0) return 0.0;
    double g = x > 1.0 ? x : 1.0;
    for (int i = 0; i < 80; ++i) g = 0.5 * (g + x / g);
    return g;
}

struct Tbl { float pk[NBETA][DIM]; float pw[NBETA][DIM]; };

__host__ __device__ constexpr Tbl make_tbl() {
    constexpr double PI_ = 3.14159265358979323846;
    constexpr double GLX[NBETA] = {
        -0.9815606342467192, -0.9041172563704749, -0.7699026741943047,
        -0.5873179542866175, -0.3678314989981802, -0.1252334085114689,
         0.1252334085114689,  0.3678314989981802,  0.5873179542866175,
         0.7699026741943047,  0.9041172563704749,  0.9815606342467192 };
    constexpr double GLW[NBETA] = {
        0.0471753363865118, 0.1069393259953184, 0.1600783285433462,
        0.2031674267230659, 0.2334925365383548, 0.2491470458134028,
        0.2491470458134028, 0.2334925365383548, 0.2031674267230659,
        0.1600783285433462, 0.1069393259953184, 0.0471753363865118 };
    Tbl T{};
    for (int b = 0; b < NBETA; ++b) {
        double x = GLX[b], w = GLW[b];
        double P[6][6] = {};
        double s = csqrt_(1.0 - x * x);
        P[0][0] = csqrt_(1.0 / (4.0 * PI_));
        for (int m = 1; m <= 5; ++m)
            P[m][m] = csqrt_((2.0 * m + 1.0) / (2.0 * m)) * s * P[m - 1][m - 1];
        for (int m = 0; m < 5; ++m)
            P[m + 1][m] = csqrt_(2.0 * m + 3.0) * x * P[m][m];
        for (int m = 0; m <= 5; ++m)
            for (int l = m + 2; l <= 5; ++l) {
                double aa = csqrt_((4.0 * l * l - 1.0) / ((double)l * l - (double)m * m));
                double bb = csqrt_((((l - 1.0) * (l - 1.0)) - (double)m * m) /
                                   (4.0 * (l - 1.0) * (l - 1.0) - 1.0));
                P[l][m] = aa * (x * P[l - 1][m] - bb * P[l - 2][m]);
            }
        double wfac = w * (2.0 * PI_ / (double)NALPHA);
        for (int k = 0; k < DIM; ++k) {
            int l = 0;
            while (k >= (l + 1) * (l + 1)) ++l;
            int m = k - l * l - l;
            int am = m < 0 ? -m : m;
            T.pk[b][k] = (float)P[l][am];
            T.pw[b][k] = (float)(P[l][am] * wfac);
        }
    }
    return T;
}

// alpha trig immediates
#define CA1 1.4142135623730951f
#define CAH 0.7071067811865476f
#define CAQ 1.2247448713915890f

#define HDR 16   // smem floats before fg (atype staging)

// ---------------------------------------------------------------------------
// Main kernel: block = 1 atom, thread = 1 channel, 3 blocks/SM.
// ALL tables are compile-time immediates (FFMA-imm, rt=1); zero table LDS.
// b-loops fully unrolled. ap region: both alpha symmetries (round-14 form).
// fp16x2 fg cache is the only smem traffic in the hot path.
// ---------------------------------------------------------------------------
__global__ __launch_bounds__(NCH, 3) void tp_main_kernel(
    const float* __restrict__ feat,    // [n, 128, 36]
    const float* __restrict__ atype,   // [n, 10]
    const float* __restrict__ W,       // [3, 10, 128, 6]
    float* __restrict__ out)           // [n, 128, 36]
{
    constexpr Tbl T = make_tbl();
    constexpr int KM[DIM] = {5,
                             4,5,6,
                             3,4,5,6,7,
                             2,3,4,5,6,7,8,
                             1,2,3,4,5,6,7,8,9,
                             0,1,2,3,4,5,6,7,8,9,10};
    constexpr int KL[DIM] = {0,
                             1,1,1,
                             2,2,2,2,2,
                             3,3,3,3,3,3,3,
                             4,4,4,4,4,4,4,4,4,
                             5,5,5,5,5,5,5,5,5,5,5};

    extern __shared__ float sm[];
    float*   sAt = sm;
    __half2* sFg = reinterpret_cast<__half2*>(sm + HDR);   // [b*6+ap][tid]

    const int tid = threadIdx.x;
    const int n   = blockIdx.x;

    if (tid < NTYPE) sAt[tid] = atype[(size_t)n * NTYPE + tid];
    __syncthreads();

    const size_t base = ((size_t)n * NCH + tid) * DIM;

    // ---- load coefficients ----
    float c0[DIM];
    {
        const float4* fp = reinterpret_cast<const float4*>(feat + base);
        #pragma unroll
        for (int q = 0; q < 9; ++q) {
            float4 v = fp[q];
            c0[4*q+0] = v.x; c0[4*q+1] = v.y; c0[4*q+2] = v.z; c0[4*q+3] = v.w;
        }
    }

    // =================== pass A: fg = Y c0 ; p1 = Yw^T (fg*fg) ===============
    float p1[DIM];
    #pragma unroll
    for (int k = 0; k < DIM; ++k) p1[k] = 0.f;

    #pragma unroll
    for (int b = 0; b < NBETA; ++b) {
        float t[11];
        #pragma unroll
        for (int mi = 0; mi < 11; ++mi) t[mi] = 0.f;
        #pragma unroll
        for (int k = 0; k < DIM; ++k)
            t[KM[k]] = fmaf(T.pk[b][k], c0[k], t[KM[k]]);

        float u[11];
        #pragma unroll
        for (int mi = 0; mi < 11; ++mi) u[mi] = 0.f;
        __half2* fgrow = sFg + b * NAPAIR * NCH + tid;

        // ---- singleton ap=0 (alpha=0) ----
        {
            float fe = fmaf(CA1, t[7], fmaf(CA1, t[9], t[5]));
            float fo = fmaf(CA1, t[6], fmaf(CA1, t[8], CA1 * t[10]));
            float f1 = fe + fo, f2 = fe - fo;
            fgrow[0 * NCH] = __floats2half2_rn(f1, f2);
            float q1 = f1 * f1, q2 = f2 * f2;
            float gs = q1 + q2, gd = q1 - q2;
            u[5] += gs;
            u[7] = fmaf(gs, CA1, u[7]);  u[9]  = fmaf(gs, CA1, u[9]);
            u[6] = fmaf(gd, CA1, u[6]);  u[8]  = fmaf(gd, CA1, u[8]);
            u[10] = fmaf(gd, CA1, u[10]);
        }
        // ---- singleton ap=3 (alpha=pi/2) ----
        {
            float fe = fmaf(-CA1, t[7], fmaf(CA1, t[9], t[5]));
            float fo = fmaf(CA1, t[0], fmaf(-CA1, t[2], CA1 * t[4]));
            float f1 = fe + fo, f2 = fe - fo;
            fgrow[3 * NCH] = __floats2half2_rn(f1, f2);
            float q1 = f1 * f1, q2 = f2 * f2;
            float gs = q1 + q2, gd = q1 - q2;
            u[5] += gs;
            u[7] = fmaf(gs, -CA1, u[7]);  u[9] = fmaf(gs, CA1, u[9]);
            u[0] = fmaf(gd, CA1, u[0]);   u[2] = fmaf(gd, -CA1, u[2]);
            u[4] = fmaf(gd, CA1, u[4]);
        }
        // ---- group {1,5} ----
        {
            float feC = fmaf(CAH, t[7], fmaf(-CAH, t[9], t[5]));
            float feS = fmaf(CAQ, t[1], CAQ * t[3]);
            float foC = fmaf(-CAQ, t[10], CAQ * t[6]);
            float foS = fmaf(CAH, t[0], fmaf(CA1, t[2], CAH * t[4]));
            float fea = feC + feS, foa = foC + foS;
            float feb = feC - feS, fob = foS - foC;
            float f1a = fea + foa, f2a = fea - foa;
            float f1b = feb + fob, f2b = feb - fob;
            fgrow[1 * NCH] = __floats2half2_rn(f1a, f2a);
            fgrow[5 * NCH] = __floats2half2_rn(f1b, f2b);
            float qa1 = f1a * f1a, qa2 = f2a * f2a;
            float qb1 = f1b * f1b, qb2 = f2b * f2b;
            float gsa = qa1 + qa2, gda = qa1 - qa2;
            float gsb = qb1 + qb2, gdb = qb1 - qb2;
            float gsP = gsa + gsb, gsM = gsa - gsb;
            float gdP = gda + gdb, gdM = gda - gdb;
            u[5] += gsP;
            u[7] = fmaf(gsP, CAH, u[7]);   u[9]  = fmaf(gsP, -CAH, u[9]);
            u[1] = fmaf(gsM, CAQ, u[1]);   u[3]  = fmaf(gsM, CAQ, u[3]);
            u[0] = fmaf(gdP, CAH, u[0]);   u[2]  = fmaf(gdP, CA1, u[2]);
            u[4] = fmaf(gdP, CAH, u[4]);
            u[6] = fmaf(gdM, CAQ, u[6]);   u[10] = fmaf(gdM, -CAQ, u[10]);
        }
        // ---- group {2,4} ----
        {
            float feC = fmaf(-CAH, t[7], fmaf(-CAH, t[9], t[5]));
            float feS = fmaf(-CAQ, t[1], CAQ * t[3]);
            float foC = fmaf(CAH, t[6], fmaf(-CA1, t[8], CAH * t[10]));
            float foS = fmaf(-CAQ, t[0], CAQ * t[4]);
            float fea = feC + feS, foa = foC + foS;
            float feb = feC - feS, fob = foS - foC;
            float f1a = fea + foa, f2a = fea - foa;
            float f1b = feb + fob, f2b = feb - fob;
            fgrow[2 * NCH] = __floats2half2_rn(f1a, f2a);
            fgrow[4 * NCH] = __floats2half2_rn(f1b, f2b);
            float qa1 = f1a * f1a, qa2 = f2a * f2a;
            float qb1 = f1b * f1b, qb2 = f2b * f2b;
            float gsa = qa1 + qa2, gda = qa1 - qa2;
            float gsb = qb1 + qb2, gdb = qb1 - qb2;
            float gsP = gsa + gsb, gsM = gsa - gsb;
            float gdP = gda + gdb, gdM = gda - gdb;
            u[5] += gsP;
            u[7] = fmaf(gsP, -CAH, u[7]);  u[9]  = fmaf(gsP, -CAH, u[9]);
            u[1] = fmaf(gsM, -CAQ, u[1]);  u[3]  = fmaf(gsM, CAQ, u[3]);
            u[0] = fmaf(gdP, -CAQ, u[0]);  u[4]  = fmaf(gdP, CAQ, u[4]);
            u[6] = fmaf(gdM, CAH, u[6]);   u[8]  = fmaf(gdM, -CA1, u[8]);
            u[10] = fmaf(gdM, CAH, u[10]);
        }

        #pragma unroll
        for (int k = 0; k < DIM; ++k)
            p1[k] = fmaf(T.pw[b][k], u[KM[k]], p1[k]);
    }

    // ============ pass B: p2 = Yw^T ((Y p1) * fg) ============================
    float p2[DIM];
    #pragma unroll
    for (int k = 0; k < DIM; ++k) p2[k] = 0.f;

    #pragma unroll
    for (int b = 0; b < NBETA; ++b) {
        float t[11];
        #pragma unroll
        for (int mi = 0; mi < 11; ++mi) t[mi] = 0.f;
        #pragma unroll
        for (int k = 0; k < DIM; ++k)
            t[KM[k]] = fmaf(T.pk[b][k], p1[k], t[KM[k]]);

        float u[11];
        #pragma unroll
        for (int mi = 0; mi < 11; ++mi) u[mi] = 0.f;
        const __half2* fgrow = sFg + b * NAPAIR * NCH + tid;

        // ---- singleton ap=0 ----
        {
            float fe = fmaf(CA1, t[7], fmaf(CA1, t[9], t[5]));
            float fo = fmaf(CA1, t[6], fmaf(CA1, t[8], CA1 * t[10]));
            float2 fg = __half22float2(fgrow[0 * NCH]);
            float g1 = (fe + fo) * fg.x, g2 = (fe - fo) * fg.y;
            float gs = g1 + g2, gd = g1 - g2;
            u[5] += gs;
            u[7] = fmaf(gs, CA1, u[7]);  u[9]  = fmaf(gs, CA1, u[9]);
            u[6] = fmaf(gd, CA1, u[6]);  u[8]  = fmaf(gd, CA1, u[8]);
            u[10] = fmaf(gd, CA1, u[10]);
        }
        // ---- singleton ap=3 ----
        {
            float fe = fmaf(-CA1, t[7], fmaf(CA1, t[9], t[5]));
            float fo = fmaf(CA1, t[0], fmaf(-CA1, t[2], CA1 * t[4]));
            float2 fg = __half22float2(fgrow[3 * NCH]);
            float g1 = (fe + fo) * fg.x, g2 = (fe - fo) * fg.y;
            float gs = g1 + g2, gd = g1 - g2;
            u[5] += gs;
            u[7] = fmaf(gs, -CA1, u[7]);  u[9] = fmaf(gs, CA1, u[9]);
            u[0] = fmaf(gd, CA1, u[0]);   u[2] = fmaf(gd, -CA1, u[2]);
            u[4] = fmaf(gd, CA1, u[4]);
        }
        // ---- group {1,5} ----
        {
            float feC = fmaf(CAH, t[7], fmaf(-CAH, t[9], t[5]));
            float feS = fmaf(CAQ, t[1], CAQ * t[3]);
            float foC = fmaf(-CAQ, t[10], CAQ * t[6]);
            float foS = fmaf(CAH, t[0], fmaf(CA1, t[2], CAH * t[4]));
            float fea = feC + feS, foa = foC + foS;
            float feb = feC - feS, fob = foS - foC;
            float2 fga = __half22float2(fgrow[1 * NCH]);
            float2 fgb = __half22float2(fgrow[5 * NCH]);
            float g1a = (fea + foa) * fga.x, g2a = (fea - foa) * fga.y;
            float g1b = (feb + fob) * fgb.x, g2b = (feb - fob) * fgb.y;
            float gsa = g1a + g2a, gda = g1a - g2a;
            float gsb = g1b + g2b, gdb = g1b - g2b;
            float gsP = gsa + gsb, gsM = gsa - gsb;
            float gdP = gda + gdb, gdM = gda - gdb;
            u[5] += gsP;
            u[7] = fmaf(gsP, CAH, u[7]);   u[9]  = fmaf(gsP, -CAH, u[9]);
            u[1] = fmaf(gsM, CAQ, u[1]);   u[3]  = fmaf(gsM, CAQ, u[3]);
            u[0] = fmaf(gdP, CAH, u[0]);   u[2]  = fmaf(gdP, CA1, u[2]);
            u[4] = fmaf(gdP, CAH, u[4]);
            u[6] = fmaf(gdM, CAQ, u[6]);   u[10] = fmaf(gdM, -CAQ, u[10]);
        }
        // ---- group {2,4} ----
        {
            float feC = fmaf(-CAH, t[7], fmaf(-CAH, t[9], t[5]));
            float feS = fmaf(-CAQ, t[1], CAQ * t[3]);
            float foC = fmaf(CAH, t[6], fmaf(-CA1, t[8], CAH * t[10]));
            float foS = fmaf(-CAQ, t[0], CAQ * t[4]);
            float fea = feC + feS, foa = foC + foS;
            float feb = feC - feS, fob = foS - foC;
            float2 fga = __half22float2(fgrow[2 * NCH]);
            float2 fgb = __half22float2(fgrow[4 * NCH]);
            float g1a = (fea + foa) * fga.x, g2a = (fea - foa) * fga.y;
            float g1b = (feb + fob) * fgb.x, g2b = (feb - fob) * fgb.y;
            float gsa = g1a + g2a, gda = g1a - g2a;
            float gsb = g1b + g2b, gdb = g1b - g2b;
            float gsP = gsa + gsb, gsM = gsa - gsb;
            float gdP = gda + gdb, gdM = gda - gdb;
            u[5] += gsP;
            u[7] = fmaf(gsP, -CAH, u[7]);  u[9]  = fmaf(gsP, -CAH, u[9]);
            u[1] = fmaf(gsM, -CAQ, u[1]);  u[3]  = fmaf(gsM, CAQ, u[3]);
            u[0] = fmaf(gdP, -CAQ, u[0]);  u[4]  = fmaf(gdP, CAQ, u[4]);
            u[6] = fmaf(gdM, CAH, u[6]);   u[8]  = fmaf(gdM, -CA1, u[8]);
            u[10] = fmaf(gdM, CAH, u[10]);
        }

        #pragma unroll
        for (int k = 0; k < DIM; ++k)
            p2[k] = fmaf(T.pw[b][k], u[KM[k]], p2[k]);
    }

    // ---- weights ----
    float w0[6], w1[6], w2[6];
    #pragma unroll
    for (int l = 0; l < 6; ++l) { w0[l] = 0.f; w1[l] = 0.f; w2[l] = 0.f; }
    #pragma unroll 1
    for (int e = 0; e < NTYPE; ++e) {
        float a = sAt[e];
        const float* Wp = W + ((size_t)e * NCH + tid) * 6;
        #pragma unroll
        for (int l = 0; l < 6; ++l) {
            w0[l] = fmaf(a, Wp[l],                       w0[l]);
            w1[l] = fmaf(a, Wp[NTYPE * NCH * 6 + l],     w1[l]);
            w2[l] = fmaf(a, Wp[2 * NTYPE * NCH * 6 + l], w2[l]);
        }
    }

    // ---- final combine: reload c0 + vectorized store ----
    const float4* fp = reinterpret_cast<const float4*>(feat + base);
    float* op = out + base;
    #pragma unroll
    for (int q = 0; q < 9; ++q) {
        float4 cv = fp[q];
        float4 v;
        v.x = fmaf(w0[KL[4*q+0]], cv.x, fmaf(w1[KL[4*q+0]], p1[4*q+0], w2[KL[4*q+0]] * p2[4*q+0]));
        v.y = fmaf(w0[KL[4*q+1]], cv.y, fmaf(w1[KL[4*q+1]], p1[4*q+1], w2[KL[4*q+1]] * p2[4*q+1]));
        v.z = fmaf(w0[KL[4*q+2]], cv.z, fmaf(w1[KL[4*q+2]], p1[4*q+2], w2[KL[4*q+2]] * p2[4*q+2]));
        v.w = fmaf(w0[KL[4*q+3]], cv.w, fmaf(w1[KL[4*q+3]], p1[4*q+3], w2[KL[4*q+3]] * p2[4*q+3]));
        *reinterpret_cast<float4*>(op + 4 * q) = v;
    }
}

// ---------------------------------------------------------------------------
extern "C" void kernel_launch(void* const* d_in, const int* in_sizes, int n_in,
                              void* d_out, int out_size) {
    // Bind inputs BY SIZE: feat = largest (n*128*36), W = 23040, atype = n*10
    const float* feat  = nullptr;
    const float* atype = nullptr;
    const float* W     = nullptr;

    int fi = 0;
    for (int i = 1; i < n_in; ++i) if (in_sizes[i] > in_sizes[fi]) fi = i;
    feat = (const float*)d_in[fi];
    int n_atoms = in_sizes[fi] / (NCH * DIM);

    for (int i = 0; i < n_in; ++i) {
        if (i == fi) continue;
        if (in_sizes[i] == WSIZE && W == nullptr && in_sizes[i] != n_atoms * NTYPE) {
            W = (const float*)d_in[i];
        } else if (in_sizes[i] == n_atoms * NTYPE && atype == nullptr) {
            atype = (const float*)d_in[i];
        } else if (W == nullptr) {
            W = (const float*)d_in[i];
        } else {
            atype = (const float*)d_in[i];
        }
    }
    if (!atype) atype = (const float*)d_in[1];
    if (!W)     W     = (const float*)d_in[2];

    float* out = (float*)d_out;

    // smem: HDR floats + 12*6*128 half2 fg = 64 + 36864 = 36928 B
    size_t smem = (size_t)HDR * sizeof(float) +
                  (size_t)NBETA * NAPAIR * NCH * sizeof(__half2);
    cudaFuncSetAttribute(tp_main_kernel,
                         cudaFuncAttributeMaxDynamicSharedMemorySize, (int)smem);

    tp_main_kernel<<<n_atoms, NCH, smem>>>(feat, atype, W, out);
}